// round 15
// baseline (speedup 1.0000x reference)
#include <cuda_runtime.h>
#include <cuda_fp16.h>
#include <math.h>
#include <math_constants.h>
#include <cstdint>

#define BB 2
#define SS 2048
#define DD 1024
#define FF 64
#define TT 28
#define VV 50257
#define MM (BB*SS)      // 4096
#define NPAD 50432      // 197 * 256
#define KD 1024
#define K2 128
#define RPC 32          // rows per CTA in the persistent step kernel
#define XP 1032         // padded sx row pitch (floats)

// ==================== scratch (device globals; no allocation) ===============
__device__ float g_x[(size_t)MM*DD];
__device__ float g_ct[(size_t)SS*FF];
__device__ float g_st[(size_t)SS*FF];
__device__ unsigned short g_Xh[(size_t)MM*KD];     // fp16 normed x (lm A)
__device__ unsigned short g_Wh[(size_t)NPAD*KD];   // fp16 lm_head W
__device__ unsigned short g_W1h[(size_t)2*FF*KD];  // fp16 to_wave_W [128,1024]
__device__ unsigned short g_W2h[(size_t)DD*K2];    // fp16 W2^T      [1024,128]

// ==================== helpers ===============================================
__device__ __forceinline__ uint32_t smem_u32(const void* p) {
    uint32_t a;
    asm("{ .reg .u64 t; cvta.to.shared.u64 t, %1; cvt.u32.u64 %0, t; }" : "=r"(a) : "l"(p));
    return a;
}
__device__ __forceinline__ void cp16(uint32_t dst, const void* src) {
    asm volatile("cp.async.cg.shared.global [%0], [%1], 16;\n" :: "r"(dst), "l"(src) : "memory");
}
__device__ __forceinline__ void cp_commit() { asm volatile("cp.async.commit_group;\n" ::: "memory"); }

__device__ __forceinline__ void ldm_x4(uint32_t* r, uint32_t addr) {
    asm volatile("ldmatrix.sync.aligned.m8n8.x4.shared.b16 {%0,%1,%2,%3}, [%4];"
        : "=r"(r[0]), "=r"(r[1]), "=r"(r[2]), "=r"(r[3]) : "r"(addr));
}
__device__ __forceinline__ void mma16816(float* d, const uint32_t* a, const uint32_t* b) {
    asm volatile("mma.sync.aligned.m16n8k16.row.col.f32.f16.f16.f32 "
        "{%0,%1,%2,%3}, {%4,%5,%6,%7}, {%8,%9}, {%0,%1,%2,%3};"
        : "+f"(d[0]), "+f"(d[1]), "+f"(d[2]), "+f"(d[3])
        : "r"(a[0]), "r"(a[1]), "r"(a[2]), "r"(a[3]), "r"(b[0]), "r"(b[1]));
}

// ==================== one-time precompute ===================================
__global__ void k_prep_w2h(const float* __restrict__ speed,
                           const float* __restrict__ dampen,
                           const float* __restrict__ phase,
                           const float* __restrict__ coupling,
                           const float* __restrict__ fwW) {
    int idx = blockIdx.x * blockDim.x + threadIdx.x;
    if (idx >= DD*K2) return;
    int d = idx >> 7, j = idx & 127;
    int f = j & (FF-1);
    float dmp = dampen[f];
    float sp  = (dmp > 20.f) ? dmp : log1pf(expf(dmp));
    float m   = expf(-sp);
    float th  = speed[f] * CUDART_PI_F + phase[f];
    float c, s; sincosf(th, &s, &c);
    float coef = (j < FF) ? (m * c) : (-m * s);
    float acc = 0.f;
    #pragma unroll 8
    for (int g = 0; g < FF; g++) acc += coupling[f*FF+g] * fwW[d*FF+g];
    ((__half*)g_W2h)[idx] = __float2half_rn(coef * acc);
}

__global__ void k_convW1h(const float* __restrict__ toW) {
    int f = blockIdx.x;
    int tid = threadIdx.x;
    float4 w = *(const float4*)(toW + (size_t)f*DD + tid*4);
    __half2* p = (__half2*)(g_W1h + (size_t)f*KD + tid*4);
    p[0] = __half2{__float2half_rn(w.x), __float2half_rn(w.y)};
    p[1] = __half2{__float2half_rn(w.z), __float2half_rn(w.w)};
}

__global__ void k_tables(const float* __restrict__ pf) {
    int idx = blockIdx.x * blockDim.x + threadIdx.x;
    if (idx >= SS*FF) return;
    int s = idx / FF, f = idx - s*FF;
    float th = (float)s * pf[f];
    float sn, cs; sincosf(th, &sn, &cs);
    g_ct[idx] = cs;
    g_st[idx] = sn;
}

__global__ void k_embed(const int* __restrict__ tokens,
                        const float* __restrict__ embW) {
    int r = blockIdx.x;
    int t = tokens[r];
    const float4* src = (const float4*)(embW + (size_t)t * DD);
    float4* dst = (float4*)(g_x + (size_t)r * DD);
    dst[threadIdx.x] = src[threadIdx.x];
}

__global__ void k_convWh(const float* __restrict__ lmW) {
    int v = blockIdx.x;
    int tid = threadIdx.x;
    float4 w = make_float4(0.f, 0.f, 0.f, 0.f);
    if (v < VV) w = *(const float4*)(lmW + (size_t)v*DD + tid*4);
    __half2* p = (__half2*)(g_Wh + (size_t)v*KD + tid*4);
    p[0] = __half2{__float2half_rn(w.x), __float2half_rn(w.y)};
    p[1] = __half2{__float2half_rn(w.z), __float2half_rn(w.w)};
}

// ==================== persistent step kernel ================================
// 128 CTAs x 256 threads; CTA owns 32 rows of x resident in smem.
// Fewer/fatter iterations — gemm1 BK=128 (8 iters), gemm2 128-col chunks
// (8 iters). 2-stage 32KB B ring. Rotation tables + norm weights read straight
// from L2 (no smem copies). Bit-identical arithmetic to R13.
//
// smem layout (bytes):
#define O_SX    0                         // 32 x 1032 fp32 = 132096
#define O_RV    132096                    // rinv 32 fp32 (+pad) = 128
#define O_AZ    132224                    // A dbl-buf 2x8192 / ZH 2x4096 = 16384
#define O_BST   148608                    // B ring 2 x 32768 = 65536
#define O_WC    (O_BST + 32768)           // wc staging 32x132x4=16896, aliases ring st1
#define STEP_SMEM 214144
#define WCP 132

__global__ void __launch_bounds__(256, 1)
k_step(const float* __restrict__ normsW,
       const float* __restrict__ stepsc,
       const float* __restrict__ onw) {
    extern __shared__ __align__(128) char smem[];
    uint32_t sb = smem_u32(smem);
    float* SX  = (float*)smem;
    float* RV  = (float*)(smem + O_RV);
    float* WC  = (float*)(smem + O_WC);

    int tid = threadIdx.x, lane = tid & 31, wid = tid >> 5;
    int r0 = blockIdx.x * RPC;
    int arow = tid >> 3, au = tid & 7;     // 8 threads per owned row

    // ---- init: x rows into smem -------------------------------------------
    for (int i = tid; i < RPC*256; i += 256) {       // 8192 float4
        int row = i >> 8, c4 = i & 255;
        *(float4*)(SX + (size_t)row*XP + c4*4) =
            ((const float4*)(g_x + (size_t)(r0+row)*DD))[c4];
    }
    __syncthreads();

    int warp_m1 = wid & 1, warp_n1 = wid >> 1;
    int lrow = ((lane >> 3) & 1) * 8 + (lane & 7);
    int uadd = lane >> 4;
    int rA1 = warp_m1*16 + lrow, sA1 = rA1 & 7;
    int rB1 = warp_n1*32 + lrow, sB1 = rB1 & 7;
    int rA2 = warp_m1*16 + lrow, sA2 = rA2 & 7;
    int rB2 = warp_n1*16 + lrow, sB2 = rB2 & 7;

    const float* xr = SX + (size_t)arow*XP;
    int srot = (r0 + arow) & (SS-1);

    // B1 stage: two 64-col sub-tiles (128 rows x 128B each) = 32 KB
    auto issueB1 = [&](int it, int stg) {
        uint32_t st = sb + O_BST + stg*32768;
        #pragma unroll
        for (int j = 0; j < 8; j++) {
            int idx = tid + j*256;               // 2048 = 2 subs x 128 rows x 8 units
            int s = idx >> 10, rem = idx & 1023;
            int row = rem >> 3, u = rem & 7;
            cp16(st + s*16384 + row*128 + ((u ^ (row & 7)) << 4),
                 (const char*)g_W1h + ((size_t)row*KD + it*128 + s*64 + u*8) * 2);
        }
        cp_commit();
    };
    // B2 stage: 2 n-chunks x 2 k-planes x 64 rows x 128B = 32 KB
    auto issueB2 = [&](int p, int stg) {
        uint32_t st = sb + O_BST + stg*32768;
        #pragma unroll
        for (int j = 0; j < 8; j++) {
            int idx = tid + j*256;
            int c = idx >> 10, rem = idx & 1023;
            int kc = rem >> 9, r2 = rem & 511;
            int row = r2 >> 3, u = r2 & 7;
            cp16(st + c*16384 + kc*8192 + row*128 + ((u ^ (row & 7)) << 4),
                 (const char*)g_W2h + ((size_t)((p*2+c)*64+row)*K2 + kc*64 + u*8) * 2);
        }
        cp_commit();
    };

    for (int t = 0; t < TT; t++) {
        const float* nwp = normsW + (size_t)t*DD;
        issueB1(0, 0); issueB1(1, 1);               // deep pre-issue over rms

        // ---- rms -----------------------------------------------------------
        float sum = 0.f;
        #pragma unroll
        for (int kt = 0; kt < 16; kt++) {
            float4 a = *(const float4*)(xr + kt*64 + au*8);
            float4 b = *(const float4*)(xr + kt*64 + au*8 + 4);
            sum += a.x*a.x + a.y*a.y + a.z*a.z + a.w*a.w
                 + b.x*b.x + b.y*b.y + b.z*b.z + b.w*b.w;
        }
        #pragma unroll
        for (int o = 1; o < 8; o <<= 1) sum += __shfl_xor_sync(0xffffffffu, sum, o);
        if (au == 0) RV[arow] = rsqrtf(sum * (1.f/DD) + 1.1920929e-7f);
        __syncthreads();
        float ri = RV[arow];

        // ---- gemm1: wc = (x*ri*nw) @ W1h^T  (BK=128, 8 iters) -------------
        float acc1[4][4] = {};
        #pragma unroll 1
        for (int it = 0; it < 8; it++) {
            #pragma unroll
            for (int s = 0; s < 2; s++) {        // C(it): convert 128 cols
                const float* xp = xr + it*128 + s*64 + au*8;
                float4 a = *(const float4*)xp;
                float4 b = *(const float4*)(xp + 4);
                float4 n0 = __ldg((const float4*)(nwp + it*128 + s*64 + au*8));
                float4 n1 = __ldg((const float4*)(nwp + it*128 + s*64 + au*8 + 4));
                __half2 h0{__float2half_rn(a.x*ri*n0.x), __float2half_rn(a.y*ri*n0.y)};
                __half2 h1{__float2half_rn(a.z*ri*n0.z), __float2half_rn(a.w*ri*n0.w)};
                __half2 h2{__float2half_rn(b.x*ri*n1.x), __float2half_rn(b.y*ri*n1.y)};
                __half2 h3{__float2half_rn(b.z*ri*n1.z), __float2half_rn(b.w*ri*n1.w)};
                uint4 pk;
                pk.x = *(uint32_t*)&h0; pk.y = *(uint32_t*)&h1;
                pk.z = *(uint32_t*)&h2; pk.w = *(uint32_t*)&h3;
                *(uint4*)(smem + O_AZ + (it&1)*8192 + s*4096
                          + arow*128 + ((au ^ (arow&7)) << 4)) = pk;
            }
            if (it < 7) asm volatile("cp.async.wait_group 1;" ::: "memory");
            else        asm volatile("cp.async.wait_group 0;" ::: "memory");
            __syncthreads();                      // S(it): A buf + B stage ready
            uint32_t stA = sb + O_AZ + (it&1)*8192 + rA1*128;
            uint32_t stB = sb + O_BST + (it&1)*32768 + rB1*128;
            #pragma unroll
            for (int kk = 0; kk < 8; kk++) {      // M(it)
                int sub = kk >> 2, kkl = kk & 3;
                uint32_t af[4], bf[2][4];
                ldm_x4(af, stA + sub*4096 + (((kkl*2 + uadd) ^ sA1) << 4));
                #pragma unroll
                for (int nt = 0; nt < 2; nt++)
                    ldm_x4(bf[nt], stB + sub*16384 + nt*2048 + (((kkl*2 + uadd) ^ sB1) << 4));
                #pragma unroll
                for (int nr = 0; nr < 4; nr++) {
                    uint32_t b2[2] = { bf[nr>>1][nr & 1], bf[nr>>1][(nr & 1) + 2] };
                    mma16816(acc1[nr], af, b2);
                }
            }
            __syncthreads();                      // S2(it): stage free for rewrite
            if (it + 2 < 8) issueB1(it + 2, it & 1);
        }

        // wc fragments -> WC (aliases ring st1; all gemm1 reads + groups done)
        {
            int orow = warp_m1*16 + (lane >> 2);
            int ocol = warp_n1*32 + (lane & 3)*2;
            #pragma unroll
            for (int nr = 0; nr < 4; nr++) {
                int cc = ocol + (nr >> 1)*16 + (nr & 1)*8;
                WC[orow*WCP + cc]     = acc1[nr][0];
                WC[orow*WCP + cc + 1] = acc1[nr][1];
                WC[(orow+8)*WCP + cc]     = acc1[nr][2];
                WC[(orow+8)*WCP + cc + 1] = acc1[nr][3];
            }
        }
        __syncthreads();
        issueB2(0, 0);                            // st0: lands during rotate

        // ---- rotate + fp16 convert -> ZH (tables straight from L2) --------
        {
            int f0 = au*8;
            const float* wr = WC + arow*WCP;
            float4 a0 = *(const float4*)(wr + f0);
            float4 a1 = *(const float4*)(wr + f0 + 4);
            float4 b0 = *(const float4*)(wr + 64 + f0);
            float4 b1 = *(const float4*)(wr + 64 + f0 + 4);
            float4 c0 = __ldg((const float4*)(g_ct + (size_t)srot*FF + f0));
            float4 c1 = __ldg((const float4*)(g_ct + (size_t)srot*FF + f0 + 4));
            float4 s0 = __ldg((const float4*)(g_st + (size_t)srot*FF + f0));
            float4 s1 = __ldg((const float4*)(g_st + (size_t)srot*FF + f0 + 4));
            __half2 r0h{__float2half_rn(a0.x*c0.x - b0.x*s0.x), __float2half_rn(a0.y*c0.y - b0.y*s0.y)};
            __half2 r1h{__float2half_rn(a0.z*c0.z - b0.z*s0.z), __float2half_rn(a0.w*c0.w - b0.w*s0.w)};
            __half2 r2h{__float2half_rn(a1.x*c1.x - b1.x*s1.x), __float2half_rn(a1.y*c1.y - b1.y*s1.y)};
            __half2 r3h{__float2half_rn(a1.z*c1.z - b1.z*s1.z), __float2half_rn(a1.w*c1.w - b1.w*s1.w)};
            __half2 i0h{__float2half_rn(a0.x*s0.x + b0.x*c0.x), __float2half_rn(a0.y*s0.y + b0.y*c0.y)};
            __half2 i1h{__float2half_rn(a0.z*s0.z + b0.z*c0.z), __float2half_rn(a0.w*s0.w + b0.w*c0.w)};
            __half2 i2h{__float2half_rn(a1.x*s1.x + b1.x*c1.x), __float2half_rn(a1.y*s1.y + b1.y*c1.y)};
            __half2 i3h{__float2half_rn(a1.z*s1.z + b1.z*c1.z), __float2half_rn(a1.w*s1.w + b1.w*c1.w)};
            uint4 zr, zi;
            zr.x = *(uint32_t*)&r0h; zr.y = *(uint32_t*)&r1h;
            zr.z = *(uint32_t*)&r2h; zr.w = *(uint32_t*)&r3h;
            zi.x = *(uint32_t*)&i0h; zi.y = *(uint32_t*)&i1h;
            zi.z = *(uint32_t*)&i2h; zi.w = *(uint32_t*)&i3h;
            uint32_t zoff = arow*128 + ((au ^ (arow&7)) << 4);
            *(uint4*)(smem + O_AZ + zoff)        = zr;   // k-plane 0
            *(uint4*)(smem + O_AZ + 4096 + zoff) = zi;   // k-plane 1
        }
        __syncthreads();                          // ZH visible; WC dead
        issueB2(1, 1);                            // st1 (overwrites WC — safe)

        // ---- gemm2: x += alpha * z @ W2h^T  (128-col chunks, 8 iters) -----
        float alpha = 0.1f * __ldg(stepsc + t);
        #pragma unroll 1
        for (int it2 = 0; it2 < 8; it2++) {
            if (it2 < 7) asm volatile("cp.async.wait_group 1;" ::: "memory");
            else         asm volatile("cp.async.wait_group 0;" ::: "memory");
            __syncthreads();                      // S(it2)
            uint32_t stg = sb + O_BST + (it2&1)*32768;
            #pragma unroll
            for (int c = 0; c < 2; c++) {         // M(it2): two 64-col chunks
                float acc2[2][4] = {};
                #pragma unroll
                for (int kc = 0; kc < 2; kc++) {
                    uint32_t stA = sb + O_AZ + kc*4096 + rA2*128;
                    uint32_t stB = stg + c*16384 + kc*8192 + rB2*128;
                    #pragma unroll
                    for (int kk = 0; kk < 4; kk++) {
                        uint32_t af[4], bf[4];
                        ldm_x4(af, stA + (((kk*2 + uadd) ^ sA2) << 4));
                        ldm_x4(bf, stB + (((kk*2 + uadd) ^ sB2) << 4));
                        #pragma unroll
                        for (int nr = 0; nr < 2; nr++) {
                            uint32_t b2[2] = { bf[nr], bf[nr + 2] };
                            mma16816(acc2[nr], af, b2);
                        }
                    }
                }
                int orow = warp_m1*16 + (lane >> 2);
                int ocol = it2*128 + c*64 + warp_n1*16 + (lane & 3)*2;
                #pragma unroll
                for (int nr = 0; nr < 2; nr++) {
                    int cc = ocol + nr*8;
                    SX[orow*XP + cc]     += alpha*acc2[nr][0];
                    SX[orow*XP + cc + 1] += alpha*acc2[nr][1];
                    SX[(orow+8)*XP + cc]     += alpha*acc2[nr][2];
                    SX[(orow+8)*XP + cc + 1] += alpha*acc2[nr][3];
                }
            }
            __syncthreads();                      // S2(it2): stage free
            if (it2 + 2 < 8) issueB2(it2 + 2, it2 & 1);
        }
        __syncthreads();                          // step end: SX consistent
    }

    // ---- final: rms with out_norm -> g_Xh ---------------------------------
    float sum = 0.f;
    #pragma unroll
    for (int kt = 0; kt < 16; kt++) {
        float4 a = *(const float4*)(xr + kt*64 + au*8);
        float4 b = *(const float4*)(xr + kt*64 + au*8 + 4);
        sum += a.x*a.x + a.y*a.y + a.z*a.z + a.w*a.w
             + b.x*b.x + b.y*b.y + b.z*b.z + b.w*b.w;
    }
    #pragma unroll
    for (int o = 1; o < 8; o <<= 1) sum += __shfl_xor_sync(0xffffffffu, sum, o);
    if (au == 0) RV[arow] = rsqrtf(sum * (1.f/DD) + 1.1920929e-7f);
    __syncthreads();
    float ri = RV[arow];
    #pragma unroll
    for (int kt = 0; kt < 16; kt++) {
        float4 a  = *(const float4*)(xr + kt*64 + au*8);
        float4 b  = *(const float4*)(xr + kt*64 + au*8 + 4);
        float4 n0 = __ldg((const float4*)(onw + kt*64 + au*8));
        float4 n1 = __ldg((const float4*)(onw + kt*64 + au*8 + 4));
        __half2 h0{__float2half_rn(a.x*ri*n0.x), __float2half_rn(a.y*ri*n0.y)};
        __half2 h1{__float2half_rn(a.z*ri*n0.z), __float2half_rn(a.w*ri*n0.w)};
        __half2 h2{__float2half_rn(b.x*ri*n1.x), __float2half_rn(b.y*ri*n1.y)};
        __half2 h3{__float2half_rn(b.z*ri*n1.z), __float2half_rn(b.w*ri*n1.w)};
        uint4 pk;
        pk.x = *(uint32_t*)&h0; pk.y = *(uint32_t*)&h1;
        pk.z = *(uint32_t*)&h2; pk.w = *(uint32_t*)&h3;
        *(uint4*)((char*)g_Xh + ((size_t)(r0+arow)*KD + kt*64 + au*8) * 2) = pk;
    }
}

// ==================== fp16 lm_head GEMM (4-stage) ===========================
#define STAGE_SZ 49152       // A 16K + B 32K
#define NSTG 4
#define NITK (KD/64)         // 16

__global__ void __launch_bounds__(512, 1) k_lm_mma(float* __restrict__ out) {
    extern __shared__ __align__(128) char smem[];
    uint32_t sb = smem_u32(smem);
    int tid = threadIdx.x;
    int lane = tid & 31, wid = tid >> 5;
    int warp_m = wid & 3, warp_n = wid >> 2;
    int r0 = blockIdx.x * 128;      // M fastest: A stays L2-resident, B streams once
    int n0 = blockIdx.y * 256;

    const char* srcA = (const char*)g_Xh + ((size_t)r0 * KD) * 2;
    const char* srcB = (const char*)g_Wh + ((size_t)n0 * KD) * 2;

    int lrow = ((lane >> 3) & 1) * 8 + (lane & 7);
    int uadd = lane >> 4;
    int rA = warp_m * 32 + lrow;
    int rB = warp_n * 64 + lrow;
    int sA = rA & 7, sB = rB & 7;
    uint32_t aBase = sb + rA * 128;
    uint32_t bBase = sb + 16384 + rB * 128;

    float acc[2][8][4] = {};

    auto issue = [&](int kt, int stg) {
        uint32_t st = sb + stg * STAGE_SZ;
        #pragma unroll
        for (int j = 0; j < 2; j++) {
            int idx = tid + j*512;
            int row = idx >> 3, u = idx & 7;
            cp16(st + row*128 + ((u ^ (row & 7)) << 4),
                 srcA + ((size_t)row*KD + kt*64 + u*8) * 2);
        }
        #pragma unroll
        for (int j = 0; j < 4; j++) {
            int idx = tid + j*512;
            int row = idx >> 3, u = idx & 7;
            cp16(st + 16384 + row*128 + ((u ^ (row & 7)) << 4),
                 srcB + ((size_t)row*KD + kt*64 + u*8) * 2);
        }
        cp_commit();
    };

    issue(0, 0); issue(1, 1); issue(2, 2);

    for (int kt = 0; kt < NITK; kt++) {
        if (kt < NITK-2)      asm volatile("cp.async.wait_group 2;" ::: "memory");
        else if (kt < NITK-1) asm volatile("cp.async.wait_group 1;" ::: "memory");
        else                  asm volatile("cp.async.wait_group 0;" ::: "memory");
        __syncthreads();
        if (kt + 3 < NITK) issue(kt + 3, (kt + 3) & 3);

        uint32_t stA = aBase + (kt & 3) * STAGE_SZ;
        uint32_t stB = bBase + (kt & 3) * STAGE_SZ;
        #pragma unroll
        for (int kk = 0; kk < 4; kk++) {
            uint32_t af[2][4], bf[4][4];
            #pragma unroll
            for (int mt = 0; mt < 2; mt++)
                ldm_x4(af[mt], stA + mt*2048 + (((kk*2 + uadd) ^ sA) << 4));
            #pragma unroll
            for (int nt = 0; nt < 4; nt++)
                ldm_x4(bf[nt], stB + nt*2048 + (((kk*2 + uadd) ^ sB) << 4));
            #pragma unroll
            for (int mt = 0; mt < 2; mt++)
                #pragma unroll
                for (int nr = 0; nr < 8; nr++) {
                    uint32_t b2[2] = { bf[nr>>1][nr & 1], bf[nr>>1][(nr & 1) + 2] };
                    mma16816(acc[mt][nr], af[mt], b2);
                }
        }
        __syncthreads();
    }

    int orow = r0 + warp_m*32 + (lane >> 2);
    int ocol = n0 + warp_n*64 + (lane & 3)*2;
    #pragma unroll
    for (int mt = 0; mt < 2; mt++) {
        #pragma unroll
        for (int nr = 0; nr < 8; nr++) {
            int cc = ocol + (nr >> 1)*16 + (nr & 1)*8;
            size_t p0 = (size_t)(orow + mt*16)     * VV + cc;
            size_t p1 = (size_t)(orow + mt*16 + 8) * VV + cc;
            if (cc < VV)     { out[p0]   = acc[mt][nr][0]; out[p1]   = acc[mt][nr][2]; }
            if (cc + 1 < VV) { out[p0+1] = acc[mt][nr][1]; out[p1+1] = acc[mt][nr][3]; }
        }
    }
}

// ==================== launch ================================================
extern "C" void kernel_launch(void* const* d_in, const int* in_sizes, int n_in,
                              void* d_out, int out_size) {
    const int*   tokens   = (const int*)  d_in[0];
    const float* embW     = (const float*)d_in[1];
    const float* toW      = (const float*)d_in[2];
    const float* fwW      = (const float*)d_in[3];
    const float* speed    = (const float*)d_in[4];
    const float* dampen   = (const float*)d_in[5];
    const float* phase    = (const float*)d_in[6];
    const float* coupling = (const float*)d_in[7];
    const float* stepsc   = (const float*)d_in[8];
    const float* posf     = (const float*)d_in[9];
    const float* normsW   = (const float*)d_in[10];
    const float* onw      = (const float*)d_in[11];
    const float* lmW      = (const float*)d_in[12];
    float* out = (float*)d_out;

    cudaFuncSetAttribute(k_lm_mma, cudaFuncAttributeMaxDynamicSharedMemorySize, NSTG*STAGE_SZ);
    cudaFuncSetAttribute(k_step,   cudaFuncAttributeMaxDynamicSharedMemorySize, STEP_SMEM);

    k_prep_w2h<<<(DD*K2 + 255)/256, 256>>>(speed, dampen, phase, coupling, fwW);
    k_convW1h<<<2*FF, 256>>>(toW);
    k_tables<<<(SS*FF + 255)/256, 256>>>(posf);
    k_embed<<<MM, 256>>>(tokens, embW);
    k_convWh<<<NPAD, 256>>>(lmW);

    k_step<<<MM/RPC, 256, STEP_SMEM>>>(normsW, stepsc, onw);

    k_lm_mma<<<dim3(MM/128, NPAD/256), 512, NSTG*STAGE_SZ>>>(out);
}